// round 14
// baseline (speedup 1.0000x reference)
#include <cuda_runtime.h>
#include <math.h>
#include <stdint.h>

#define NTOK 8192
#define DIM  1024
#define NEXP 8
#define BM   128
#define BN   128
#define BK   16
#define PADROWS (NTOK + NEXP*128)     // 9216 worst-case padded rows
#define PADTILES (PADROWS / 128)      // 72

// ---------------- device scratch (alloc-free rule) ----------------
// Reference ONLY from device code (host-side use gets the ATS host-shadow
// address — root cause of the R7-R10 anomalies).
__device__ int   g_eid[NTOK];
__device__ float g_w[NTOK];
__device__ int   g_counts[NEXP];
__device__ int   g_offs[NEXP];
__device__ int   g_padcnt[NEXP];
__device__ int   g_pperm[PADROWS];
// k-major blocked hidden activations: [tile][k][128 rows]
__device__ __align__(256) float g_h  [(size_t)PADTILES * DIM * 128];
// RNA-rounded weights (device-resident)
__device__ __align__(256) float g_w1r[(size_t)NEXP * DIM * DIM];
__device__ __align__(256) float g_w2r[(size_t)NEXP * DIM * DIM];

__device__ __forceinline__ float to_tf32(float v) {
    float r; asm("cvt.rna.tf32.f32 %0, %1;" : "=f"(r) : "f"(v)); return r;
}

// ---------------- fused prep: init counts + fill perm + round both W ----------------
__global__ void prep_kernel(const float* __restrict__ W1, const float* __restrict__ W2) {
    const int b = blockIdx.x, t = threadIdx.x;
    if (b == 0 && t < NEXP) g_counts[t] = 0;
    int pidx = b * 256 + t;
    if (pidx < PADROWS) g_pperm[pidx] = -1;

    size_t i = (size_t)b * 256 + t;                      // 0 .. 4M-1
    const size_t HALF = (size_t)NEXP * DIM * DIM / 4;    // 2M float4 per matrix
    if (i < HALF) {
        float4 v = ((const float4*)W1)[i];
        v.x = to_tf32(v.x); v.y = to_tf32(v.y); v.z = to_tf32(v.z); v.w = to_tf32(v.w);
        ((float4*)g_w1r)[i] = v;
    } else {
        size_t j = i - HALF;
        float4 v = ((const float4*)W2)[j];
        v.x = to_tf32(v.x); v.y = to_tf32(v.y); v.z = to_tf32(v.z); v.w = to_tf32(v.w);
        ((float4*)g_w2r)[j] = v;
    }
}

// ---------------- gating ----------------
__global__ void gate_kernel(const float* __restrict__ x,
                            const float* __restrict__ Wg,
                            const float* __restrict__ bg) {
    int warp = (blockIdx.x * blockDim.x + threadIdx.x) >> 5;
    int lane = threadIdx.x & 31;
    if (warp >= NTOK) return;
    const float* xr = x + (size_t)warp * DIM;
    float acc[NEXP];
#pragma unroll
    for (int e = 0; e < NEXP; e++) acc[e] = 0.f;
    for (int d = lane; d < DIM; d += 32) {
        float xv = xr[d];
        const float* wr = Wg + d * NEXP;
#pragma unroll
        for (int e = 0; e < NEXP; e++) acc[e] = fmaf(xv, wr[e], acc[e]);
    }
#pragma unroll
    for (int e = 0; e < NEXP; e++) {
#pragma unroll
        for (int o = 16; o > 0; o >>= 1)
            acc[e] += __shfl_xor_sync(0xffffffffu, acc[e], o);
    }
    if (lane == 0) {
        float l[NEXP];
        float best = -1e30f; int bi = 0;
#pragma unroll
        for (int e = 0; e < NEXP; e++) {
            l[e] = acc[e] + bg[e];
            if (l[e] > best) { best = l[e]; bi = e; }   // first-max, matches jnp.argmax
        }
        float s = 0.f;
#pragma unroll
        for (int e = 0; e < NEXP; e++) s += expf(l[e] - best);
        g_eid[warp] = bi;
        g_w[warp]   = 1.0f / s;
        atomicAdd(&g_counts[bi], 1);
    }
}

// ---------------- fused scan + scatter (single block) ----------------
__global__ void group_kernel() {
    __shared__ int sfill[NEXP];
    const int t = threadIdx.x;   // 1024 threads
    if (t == 0) {
        int o = 0;
        for (int e = 0; e < NEXP; e++) {
            int pc = ((g_counts[e] + BM - 1) / BM) * BM;
            g_padcnt[e] = pc;
            g_offs[e]   = o;
            sfill[e]    = o;
            o += pc;
        }
    }
    __syncthreads();
    for (int tok = t; tok < NTOK; tok += 1024) {
        int e = g_eid[tok];
        int pos = atomicAdd(&sfill[e], 1);
        g_pperm[pos] = tok;
    }
}

// ---------------- tf32 mma.sync grouped GEMM ----------------
// 128 threads/CTA, warp grid 2x2, warp tile 64x64 (acc 4x8x4 = 128 regs).
// Fragment smem traffic per CTA per k-iter: A*2 + B*2 = 32KB (was 48KB).
// BK=16 register-prefetch double buffer, 34816 B static smem, 2 CTAs/SM.
#define MMA_TF32(d, a, b)                                                        \
    asm volatile(                                                                \
        "mma.sync.aligned.m16n8k8.row.col.f32.tf32.tf32.f32 "                    \
        "{%0,%1,%2,%3}, {%4,%5,%6,%7}, {%8,%9}, {%0,%1,%2,%3};"                  \
        : "+f"((d)[0]), "+f"((d)[1]), "+f"((d)[2]), "+f"((d)[3])                 \
        : "r"((a)[0]), "r"((a)[1]), "r"((a)[2]), "r"((a)[3]),                    \
          "r"((b)[0]), "r"((b)[1]))

template <int STAGE>
__global__ void __launch_bounds__(128, 2)
gemm_mma(const float* __restrict__ X, const float* __restrict__ Bias,
         float* __restrict__ out) {
    __shared__ float As[2][BK][136];
    __shared__ float Bs[2][BK][136];

    const int e  = blockIdx.z;
    const int m0 = blockIdx.y * BM;
    if (m0 >= g_padcnt[e]) return;
    const int n0   = blockIdx.x * BN;
    const int off  = g_offs[e];
    const int tile = (off + m0) >> 7;

    const float* Abase = g_h + (size_t)tile * DIM * 128;                      // STAGE 2
    const float* Bbase = (STAGE == 1 ? g_w1r : g_w2r) + (size_t)e * DIM * DIM;

    const int tid  = threadIdx.x;        // 0..127
    const int lane = tid & 31;
    const int wid  = tid >> 5;           // 0..3
    const int wm   = (wid >> 1) * 64;    // 0 or 64
    const int wn   = (wid & 1) * 64;     // 0 or 64
    const int g    = lane >> 2;          // 0..7
    const int t4   = lane & 3;           // 0..3

    // staging: 512 float4 per operand tile, 4 per thread:
    // idx = i*128 + tid -> kr = 4*i + (tid>>5), ch = (tid&31)*4
    const int krA = tid >> 5;
    const int chA = (tid & 31) * 4;

    // stage-1 A gather: one x row per thread, 16 consecutive k per slab
    const float* xrow = nullptr;
    if (STAGE == 1) {
        int tokA = g_pperm[off + m0 + tid];
        if (tokA >= 0) xrow = X + (size_t)tokA * DIM;
    }

    float4 qa[4], pb[4];                 // prefetch registers

    float acc[4][8][4];
#pragma unroll
    for (int mi = 0; mi < 4; mi++)
#pragma unroll
        for (int nj = 0; nj < 8; nj++)
#pragma unroll
            for (int r = 0; r < 4; r++) acc[mi][nj][r] = 0.f;

    const int NIT = DIM / BK;   // 64

    auto loadSlab = [&](int k0) {
        if (STAGE == 1) {
            if (xrow) {
#pragma unroll
                for (int j = 0; j < 4; j++)
                    qa[j] = *(const float4*)(xrow + k0 + j * 4);
            } else {
#pragma unroll
                for (int j = 0; j < 4; j++)
                    qa[j] = make_float4(0.f, 0.f, 0.f, 0.f);
            }
        } else {
#pragma unroll
            for (int i = 0; i < 4; i++)
                qa[i] = *(const float4*)(Abase + (size_t)(k0 + 4 * i + krA) * 128 + chA);
        }
#pragma unroll
        for (int i = 0; i < 4; i++)
            pb[i] = *(const float4*)(Bbase + (size_t)(k0 + 4 * i + krA) * DIM + n0 + chA);
    };
    auto storeSlab = [&](int buf) {
        if (STAGE == 1) {
            // transpose + tf32-round into As[k][m] (row = tid)
#pragma unroll
            for (int j = 0; j < 4; j++) {
                As[buf][j * 4 + 0][tid] = to_tf32(qa[j].x);
                As[buf][j * 4 + 1][tid] = to_tf32(qa[j].y);
                As[buf][j * 4 + 2][tid] = to_tf32(qa[j].z);
                As[buf][j * 4 + 3][tid] = to_tf32(qa[j].w);
            }
        } else {
#pragma unroll
            for (int i = 0; i < 4; i++)
                *(float4*)&As[buf][4 * i + krA][chA] = qa[i];
        }
#pragma unroll
        for (int i = 0; i < 4; i++)
            *(float4*)&Bs[buf][4 * i + krA][chA] = pb[i];
    };

    // prologue
    loadSlab(0);
    storeSlab(0);
    __syncthreads();

    for (int it = 0; it < NIT; ++it) {
        const int cur = it & 1;

        if (it + 1 < NIT) loadSlab((it + 1) * BK);

        // compute current buffer (2 x K=8)
#pragma unroll
        for (int kk = 0; kk < 2; kk++) {
            const int kb = kk * 8;
            uint32_t a[4][4], b[8][2];
#pragma unroll
            for (int mi = 0; mi < 4; mi++) {
                int m = wm + mi * 16;
                a[mi][0] = __float_as_uint(As[cur][kb + t4    ][m + g    ]);
                a[mi][1] = __float_as_uint(As[cur][kb + t4    ][m + g + 8]);
                a[mi][2] = __float_as_uint(As[cur][kb + t4 + 4][m + g    ]);
                a[mi][3] = __float_as_uint(As[cur][kb + t4 + 4][m + g + 8]);
            }
#pragma unroll
            for (int nj = 0; nj < 8; nj++) {
                int n = wn + nj * 8;
                b[nj][0] = __float_as_uint(Bs[cur][kb + t4    ][n + g]);
                b[nj][1] = __float_as_uint(Bs[cur][kb + t4 + 4][n + g]);
            }
#pragma unroll
            for (int mi = 0; mi < 4; mi++)
#pragma unroll
                for (int nj = 0; nj < 8; nj++)
                    MMA_TF32(acc[mi][nj], a[mi], b[nj]);
        }

        if (it + 1 < NIT) storeSlab(cur ^ 1);
        __syncthreads();
    }

    // ---- epilogue ----
    if (STAGE == 1) {
        float* Hbase = g_h + (size_t)tile * DIM * 128;
#pragma unroll
        for (int mi = 0; mi < 4; mi++) {
            int mA = wm + mi * 16 + g;
            int mB = mA + 8;
#pragma unroll
            for (int nj = 0; nj < 8; nj++) {
                int n = n0 + wn + nj * 8 + t4 * 2;
                float bi0 = Bias[e * DIM + n];
                float bi1 = Bias[e * DIM + n + 1];
                float v0 = acc[mi][nj][0] + bi0;
                float v1 = acc[mi][nj][1] + bi1;
                float v2 = acc[mi][nj][2] + bi0;
                float v3 = acc[mi][nj][3] + bi1;
                Hbase[(size_t)n * 128 + mA]       = to_tf32(0.5f * v0 * (1.0f + erff(v0 * 0.70710678118654752f)));
                Hbase[(size_t)(n + 1) * 128 + mA] = to_tf32(0.5f * v1 * (1.0f + erff(v1 * 0.70710678118654752f)));
                Hbase[(size_t)n * 128 + mB]       = to_tf32(0.5f * v2 * (1.0f + erff(v2 * 0.70710678118654752f)));
                Hbase[(size_t)(n + 1) * 128 + mB] = to_tf32(0.5f * v3 * (1.0f + erff(v3 * 0.70710678118654752f)));
            }
        }
    } else {
        const int prow = off + m0;
#pragma unroll
        for (int mi = 0; mi < 4; mi++) {
            int mA = wm + mi * 16 + g;
            int mB = mA + 8;
            int tokA = g_pperm[prow + mA];
            int tokB = g_pperm[prow + mB];
            float wA = (tokA >= 0) ? g_w[tokA] : 0.f;
            float wB = (tokB >= 0) ? g_w[tokB] : 0.f;
#pragma unroll
            for (int nj = 0; nj < 8; nj++) {
                int n = n0 + wn + nj * 8 + t4 * 2;
                float bi0 = Bias[e * DIM + n];
                float bi1 = Bias[e * DIM + n + 1];
                if (tokA >= 0) {
                    out[(size_t)tokA * DIM + n]     = wA * (acc[mi][nj][0] + bi0);
                    out[(size_t)tokA * DIM + n + 1] = wA * (acc[mi][nj][1] + bi1);
                }
                if (tokB >= 0) {
                    out[(size_t)tokB * DIM + n]     = wB * (acc[mi][nj][2] + bi0);
                    out[(size_t)tokB * DIM + n + 1] = wB * (acc[mi][nj][3] + bi1);
                }
            }
        }
    }
}

// ---------------------------------------------------------------------------
extern "C" void kernel_launch(void* const* d_in, const int* in_sizes, int n_in,
                              void* d_out, int out_size) {
    const float* x  = (const float*)d_in[0];
    const float* Wg = (const float*)d_in[1];
    const float* bg = (const float*)d_in[2];
    const float* W1 = (const float*)d_in[3];
    const float* b1 = (const float*)d_in[4];
    const float* W2 = (const float*)d_in[5];
    const float* b2 = (const float*)d_in[6];
    float* out = (float*)d_out;

    prep_kernel<<<16384, 256>>>(W1, W2);                       // 1
    gate_kernel<<<(NTOK * 32 + 255) / 256, 256>>>(x, Wg, bg);  // 2
    group_kernel<<<1, 1024>>>();                               // 3

    dim3 grid(DIM / BN, PADTILES, NEXP);
    gemm_mma<1><<<grid, 128>>>(x, b1, nullptr);                // 4 <- profiled
    gemm_mma<2><<<grid, 128>>>(nullptr, b2, out);              // 5
}

// round 15
// speedup vs baseline: 1.0292x; 1.0292x over previous
#include <cuda_runtime.h>
#include <math.h>
#include <stdint.h>

#define NTOK 8192
#define DIM  1024
#define NEXP 8
#define BM   128
#define BN   128
#define BK   16
#define PADROWS (NTOK + NEXP*128)     // 9216 worst-case padded rows
#define PADTILES (PADROWS / 128)      // 72
#define SMEM_BYTES (2 * 4 * BK * 136 * 4)   // As[4]+Bs[4] = 69632

// ---------------- device scratch (alloc-free rule) ----------------
// Reference ONLY from device code (host-side use gets the ATS host-shadow
// address — root cause of the R7-R10 anomalies).
__device__ int   g_eid[NTOK];
__device__ float g_w[NTOK];
__device__ int   g_counts[NEXP];
__device__ int   g_offs[NEXP];
__device__ int   g_padcnt[NEXP];
__device__ int   g_pperm[PADROWS];
// k-major blocked hidden activations: [tile][k][128 rows]
__device__ __align__(256) float g_h  [(size_t)PADTILES * DIM * 128];
// RNA-rounded weights (device-resident)
__device__ __align__(256) float g_w1r[(size_t)NEXP * DIM * DIM];
__device__ __align__(256) float g_w2r[(size_t)NEXP * DIM * DIM];

__device__ __forceinline__ float to_tf32(float v) {
    float r; asm("cvt.rna.tf32.f32 %0, %1;" : "=f"(r) : "f"(v)); return r;
}
__device__ __forceinline__ uint32_t smem_u32(const void* p) {
    uint32_t a;
    asm("{ .reg .u64 t; cvta.to.shared.u64 t, %1; cvt.u32.u64 %0, t; }" : "=r"(a) : "l"(p));
    return a;
}
__device__ __forceinline__ void cp16(uint32_t s, const void* g) {
    asm volatile("cp.async.cg.shared.global [%0], [%1], 16;" :: "r"(s), "l"(g));
}

// ---------------- fused prep: init counts + fill perm + round both W ----------------
__global__ void prep_kernel(const float* __restrict__ W1, const float* __restrict__ W2) {
    const int b = blockIdx.x, t = threadIdx.x;
    if (b == 0 && t < NEXP) g_counts[t] = 0;
    int pidx = b * 256 + t;
    if (pidx < PADROWS) g_pperm[pidx] = -1;

    size_t i = (size_t)b * 256 + t;                      // 0 .. 4M-1
    const size_t HALF = (size_t)NEXP * DIM * DIM / 4;    // 2M float4 per matrix
    if (i < HALF) {
        float4 v = ((const float4*)W1)[i];
        v.x = to_tf32(v.x); v.y = to_tf32(v.y); v.z = to_tf32(v.z); v.w = to_tf32(v.w);
        ((float4*)g_w1r)[i] = v;
    } else {
        size_t j = i - HALF;
        float4 v = ((const float4*)W2)[j];
        v.x = to_tf32(v.x); v.y = to_tf32(v.y); v.z = to_tf32(v.z); v.w = to_tf32(v.w);
        ((float4*)g_w2r)[j] = v;
    }
}

// ---------------- gating ----------------
__global__ void gate_kernel(const float* __restrict__ x,
                            const float* __restrict__ Wg,
                            const float* __restrict__ bg) {
    int warp = (blockIdx.x * blockDim.x + threadIdx.x) >> 5;
    int lane = threadIdx.x & 31;
    if (warp >= NTOK) return;
    const float* xr = x + (size_t)warp * DIM;
    float acc[NEXP];
#pragma unroll
    for (int e = 0; e < NEXP; e++) acc[e] = 0.f;
    for (int d = lane; d < DIM; d += 32) {
        float xv = xr[d];
        const float* wr = Wg + d * NEXP;
#pragma unroll
        for (int e = 0; e < NEXP; e++) acc[e] = fmaf(xv, wr[e], acc[e]);
    }
#pragma unroll
    for (int e = 0; e < NEXP; e++) {
#pragma unroll
        for (int o = 16; o > 0; o >>= 1)
            acc[e] += __shfl_xor_sync(0xffffffffu, acc[e], o);
    }
    if (lane == 0) {
        float l[NEXP];
        float best = -1e30f; int bi = 0;
#pragma unroll
        for (int e = 0; e < NEXP; e++) {
            l[e] = acc[e] + bg[e];
            if (l[e] > best) { best = l[e]; bi = e; }   // first-max, matches jnp.argmax
        }
        float s = 0.f;
#pragma unroll
        for (int e = 0; e < NEXP; e++) s += expf(l[e] - best);
        g_eid[warp] = bi;
        g_w[warp]   = 1.0f / s;
        atomicAdd(&g_counts[bi], 1);
    }
}

// ---------------- fused scan + scatter (single block) ----------------
__global__ void group_kernel() {
    __shared__ int sfill[NEXP];
    const int t = threadIdx.x;   // 1024 threads
    if (t == 0) {
        int o = 0;
        for (int e = 0; e < NEXP; e++) {
            int pc = ((g_counts[e] + BM - 1) / BM) * BM;
            g_padcnt[e] = pc;
            g_offs[e]   = o;
            sfill[e]    = o;
            o += pc;
        }
    }
    __syncthreads();
    for (int tok = t; tok < NTOK; tok += 1024) {
        int e = g_eid[tok];
        int pos = atomicAdd(&sfill[e], 1);
        g_pperm[pos] = tok;
    }
}

// ---------------- tf32 mma.sync grouped GEMM, cp.async 4-stage ----------------
// 256 threads, 8 warps 64x32 (R13-proven shape). B (and stage-2 A) staged via
// cp.async.cg (L1-bypass, LDG+STS fused); stage-1 A via register gather+transpose
// one stage ahead into the same 4-buffer ring. One __syncthreads per k-iter.
#define MMA_TF32(d, a, b)                                                        \
    asm volatile(                                                                \
        "mma.sync.aligned.m16n8k8.row.col.f32.tf32.tf32.f32 "                    \
        "{%0,%1,%2,%3}, {%4,%5,%6,%7}, {%8,%9}, {%0,%1,%2,%3};"                  \
        : "+f"((d)[0]), "+f"((d)[1]), "+f"((d)[2]), "+f"((d)[3])                 \
        : "r"((a)[0]), "r"((a)[1]), "r"((a)[2]), "r"((a)[3]),                    \
          "r"((b)[0]), "r"((b)[1]))

template <int STAGE>
__global__ void __launch_bounds__(256, 2)
gemm_mma(const float* __restrict__ X, const float* __restrict__ Bias,
         float* __restrict__ out) {
    extern __shared__ float dynsm[];
    float* Asm = dynsm;                    // [4][BK][136]
    float* Bsm = dynsm + 4 * BK * 136;     // [4][BK][136]
#define AS(bf,k,m) Asm[((bf) * BK + (k)) * 136 + (m)]
#define BS(bf,k,n) Bsm[((bf) * BK + (k)) * 136 + (n)]

    const int e  = blockIdx.z;
    const int m0 = blockIdx.y * BM;
    if (m0 >= g_padcnt[e]) return;
    const int n0   = blockIdx.x * BN;
    const int off  = g_offs[e];
    const int tile = (off + m0) >> 7;

    const float* Abase = g_h + (size_t)tile * DIM * 128;                      // STAGE 2
    const float* Bbase = (STAGE == 1 ? g_w1r : g_w2r) + (size_t)e * DIM * DIM;

    const int tid  = threadIdx.x;
    const int lane = tid & 31;
    const int wid  = tid >> 5;
    const int wm   = (wid >> 2) * 64;
    const int wn   = (wid & 3) * 32;
    const int g    = lane >> 2;
    const int t4   = lane & 3;

    // cp.async staging coords: rows krA and krA+8, 16B chunk chA
    const int krA = tid >> 5;              // 0..7
    const int chA = (tid & 31) * 4;        // 0..124
    const uint32_t sB0 = smem_u32(Bsm) + (uint32_t)(krA * 136 + chA) * 4;
    const uint32_t sA0 = smem_u32(Asm) + (uint32_t)(krA * 136 + chA) * 4;
    const uint32_t bufB = (uint32_t)(BK * 136) * 4;    // bytes per buffer

    // stage-1 A gather coords: row arow, 8 consecutive k at ac2
    const int arow = tid >> 1;             // 0..127
    const int ac2  = (tid & 1) * 8;        // 0 or 8
    const float* xrow = nullptr;
    if (STAGE == 1) {
        int tokA = g_pperm[off + m0 + arow];
        if (tokA >= 0) xrow = X + (size_t)tokA * DIM;
    }
    float4 qa0, qa1;

    auto issueCp = [&](int it, int bf) {   // B always; A too in stage 2
        const int k0 = it * BK;
        cp16(sB0 + bf * bufB,                 Bbase + (size_t)(k0 + krA) * DIM + n0 + chA);
        cp16(sB0 + bf * bufB + 8 * 136 * 4,   Bbase + (size_t)(k0 + krA + 8) * DIM + n0 + chA);
        if (STAGE == 2) {
            cp16(sA0 + bf * bufB,               Abase + (size_t)(k0 + krA) * 128 + chA);
            cp16(sA0 + bf * bufB + 8 * 136 * 4, Abase + (size_t)(k0 + krA + 8) * 128 + chA);
        }
    };
    auto loadA1 = [&](int k0) {            // stage-1 A: registers
        if (xrow) {
            qa0 = *(const float4*)(xrow + k0 + ac2);
            qa1 = *(const float4*)(xrow + k0 + ac2 + 4);
        } else {
            qa0 = make_float4(0.f, 0.f, 0.f, 0.f);
            qa1 = qa0;
        }
    };
    auto storeA1 = [&](int bf) {           // transpose + tf32-round
        AS(bf, ac2 + 0, arow) = to_tf32(qa0.x);
        AS(bf, ac2 + 1, arow) = to_tf32(qa0.y);
        AS(bf, ac2 + 2, arow) = to_tf32(qa0.z);
        AS(bf, ac2 + 3, arow) = to_tf32(qa0.w);
        AS(bf, ac2 + 4, arow) = to_tf32(qa1.x);
        AS(bf, ac2 + 5, arow) = to_tf32(qa1.y);
        AS(bf, ac2 + 6, arow) = to_tf32(qa1.z);
        AS(bf, ac2 + 7, arow) = to_tf32(qa1.w);
    };

    float acc[4][4][4];
#pragma unroll
    for (int mi = 0; mi < 4; mi++)
#pragma unroll
        for (int nj = 0; nj < 4; nj++)
#pragma unroll
            for (int r = 0; r < 4; r++) acc[mi][nj][r] = 0.f;

    const int NIT = DIM / BK;   // 64

    // prologue: issue cp stages 0..2; stage-1 A slab 0 via registers
#pragma unroll
    for (int s = 0; s < 3; s++) {
        issueCp(s, s);
        asm volatile("cp.async.commit_group;");
    }
    if (STAGE == 1) { loadA1(0); storeA1(0); }

    for (int it = 0; it < NIT; ++it) {
        const int bf = it & 3;

        asm volatile("cp.async.wait_group 2;");
        __syncthreads();   // group-it data + last iter's A stores visible; buffers free

        if (STAGE == 1 && it + 1 < NIT) loadA1((it + 1) * BK);

        if (it + 3 < NIT) issueCp(it + 3, (it + 3) & 3);
        asm volatile("cp.async.commit_group;");   // empty groups at tail keep count uniform

        // compute buffer bf (2 x K=8)
#pragma unroll
        for (int kk = 0; kk < 2; kk++) {
            const int kb = kk * 8;
            uint32_t a[4][4], b[4][2];
#pragma unroll
            for (int mi = 0; mi < 4; mi++) {
                int m = wm + mi * 16;
                a[mi][0] = __float_as_uint(AS(bf, kb + t4,     m + g    ));
                a[mi][1] = __float_as_uint(AS(bf, kb + t4,     m + g + 8));
                a[mi][2] = __float_as_uint(AS(bf, kb + t4 + 4, m + g    ));
                a[mi][3] = __float_as_uint(AS(bf, kb + t4 + 4, m + g + 8));
            }
#pragma unroll
            for (int nj = 0; nj < 4; nj++) {
                int n = wn + nj * 8;
                b[nj][0] = __float_as_uint(BS(bf, kb + t4,     n + g));
                b[nj][1] = __float_as_uint(BS(bf, kb + t4 + 4, n + g));
            }
#pragma unroll
            for (int mi = 0; mi < 4; mi++)
#pragma unroll
                for (int nj = 0; nj < 4; nj++)
                    MMA_TF32(acc[mi][nj], a[mi], b[nj]);
        }

        if (STAGE == 1 && it + 1 < NIT) storeA1((it + 1) & 3);
    }

    // ---- epilogue ----
    if (STAGE == 1) {
        float* Hbase = g_h + (size_t)tile * DIM * 128;
#pragma unroll
        for (int mi = 0; mi < 4; mi++) {
            int mA = wm + mi * 16 + g;
            int mB = mA + 8;
#pragma unroll
            for (int nj = 0; nj < 4; nj++) {
                int n = n0 + wn + nj * 8 + t4 * 2;
                float bi0 = Bias[e * DIM + n];
                float bi1 = Bias[e * DIM + n + 1];
                float v0 = acc[mi][nj][0] + bi0;
                float v1 = acc[mi][nj][1] + bi1;
                float v2 = acc[mi][nj][2] + bi0;
                float v3 = acc[mi][nj][3] + bi1;
                Hbase[(size_t)n * 128 + mA]       = to_tf32(0.5f * v0 * (1.0f + erff(v0 * 0.70710678118654752f)));
                Hbase[(size_t)(n + 1) * 128 + mA] = to_tf32(0.5f * v1 * (1.0f + erff(v1 * 0.70710678118654752f)));
                Hbase[(size_t)n * 128 + mB]       = to_tf32(0.5f * v2 * (1.0f + erff(v2 * 0.70710678118654752f)));
                Hbase[(size_t)(n + 1) * 128 + mB] = to_tf32(0.5f * v3 * (1.0f + erff(v3 * 0.70710678118654752f)));
            }
        }
    } else {
        const int prow = off + m0;
#pragma unroll
        for (int mi = 0; mi < 4; mi++) {
            int mA = wm + mi * 16 + g;
            int mB = mA + 8;
            int tokA = g_pperm[prow + mA];
            int tokB = g_pperm[prow + mB];
            float wA = (tokA >= 0) ? g_w[tokA] : 0.f;
            float wB = (tokB >= 0) ? g_w[tokB] : 0.f;
#pragma unroll
            for (int nj = 0; nj < 4; nj++) {
                int n = n0 + wn + nj * 8 + t4 * 2;
                float bi0 = Bias[e * DIM + n];
                float bi1 = Bias[e * DIM + n + 1];
                if (tokA >= 0) {
                    out[(size_t)tokA * DIM + n]     = wA * (acc[mi][nj][0] + bi0);
                    out[(size_t)tokA * DIM + n + 1] = wA * (acc[mi][nj][1] + bi1);
                }
                if (tokB >= 0) {
                    out[(size_t)tokB * DIM + n]     = wB * (acc[mi][nj][2] + bi0);
                    out[(size_t)tokB * DIM + n + 1] = wB * (acc[mi][nj][3] + bi1);
                }
            }
        }
    }
#undef AS
#undef BS
}

// ---------------------------------------------------------------------------
extern "C" void kernel_launch(void* const* d_in, const int* in_sizes, int n_in,
                              void* d_out, int out_size) {
    const float* x  = (const float*)d_in[0];
    const float* Wg = (const float*)d_in[1];
    const float* bg = (const float*)d_in[2];
    const float* W1 = (const float*)d_in[3];
    const float* b1 = (const float*)d_in[4];
    const float* W2 = (const float*)d_in[5];
    const float* b2 = (const float*)d_in[6];
    float* out = (float*)d_out;

    cudaFuncSetAttribute(gemm_mma<1>, cudaFuncAttributeMaxDynamicSharedMemorySize, SMEM_BYTES);
    cudaFuncSetAttribute(gemm_mma<2>, cudaFuncAttributeMaxDynamicSharedMemorySize, SMEM_BYTES);

    prep_kernel<<<16384, 256>>>(W1, W2);                       // 1
    gate_kernel<<<(NTOK * 32 + 255) / 256, 256>>>(x, Wg, bg);  // 2
    group_kernel<<<1, 1024>>>();                               // 3

    dim3 grid(DIM / BN, PADTILES, NEXP);
    gemm_mma<1><<<grid, 256, SMEM_BYTES>>>(x, b1, nullptr);    // 4 <- profiled
    gemm_mma<2><<<grid, 256, SMEM_BYTES>>>(nullptr, b2, out);  // 5
}